// round 11
// baseline (speedup 1.0000x reference)
#include <cuda_runtime.h>

#define S_DIM 100000
#define G_DIM 18000
#define H_DIM 256
#define E_DIM 600000
#define B_DIM 256

#define NBLK    888            // 148 SMs * 6 blocks (guaranteed co-resident)
#define NTHR    256
#define G4_DIM  4500           // G_DIM/4
#define GSTRIPS 141            // ceil(4500/32)
#define BUILD_UNITS 1128       // 141 strips * 8 ktiles
#define CZ_UNITS    99         // coef-zero units (256 float4 each)
#define P1_UNITS (BUILD_UNITS + CZ_UNITS)   // 1227
#define CHUNKS  50
#define ROWS    8
#define NTILES  1600           // 50 chunks * 32 row-groups
#define C0_FIRST 870           // blocks 870..887 do const0 (1000 genes each)

// INVARIANT: g_v == 0 at kernel entry (static init; re-zeroed in phase 3 when
// v is dead). coef/out/const0 zeroed in phase 1 before their writers.
__device__ float g_v[G_DIM];
__device__ float g_coef[S_DIM];
__device__ float g_const0;
__device__ unsigned g_bar_arrive;   // static 0
__device__ unsigned g_bar_gen;      // monotonically increasing across replays

// Symmetric grid barrier: all NBLK blocks co-resident by construction.
__device__ __forceinline__ void grid_barrier() {
    __syncthreads();
    if (threadIdx.x == 0) {
        __threadfence();
        unsigned gen = *((volatile unsigned*)&g_bar_gen);
        unsigned t = atomicAdd(&g_bar_arrive, 1u);
        if (t == NBLK - 1) {
            g_bar_arrive = 0;
            __threadfence();
            atomicAdd(&g_bar_gen, 1u);
        } else {
            while (*((volatile unsigned*)&g_bar_gen) == gen) __nanosleep(64);
        }
    }
    __syncthreads();
    __threadfence();
}

__global__ void __launch_bounds__(NTHR, 6)
k_fused(const float* __restrict__ W1, const float* __restrict__ W2,
        const int* __restrict__ snp, const int* __restrict__ gidx,
        const float* __restrict__ ew, const float* __restrict__ gene_bias,
        const float* __restrict__ b1, const float* __restrict__ b2,
        const float* __restrict__ x, float* __restrict__ out) {
    const int bid = blockIdx.x;
    const int tid = threadIdx.x;
    const int tx = tid & 31;
    const int ty = tid >> 5;

    __shared__ float  w2s[32];
    __shared__ float4 red[8][32];
    float* smr = reinterpret_cast<float*>(red);   // reused for reductions

    // ======================= PHASE 1: build v + zero =======================
    for (int u = bid; u < P1_UNITS; u += NBLK) {
        if (u < BUILD_UNITS) {
            const int strip = u % GSTRIPS;
            const int k0    = (u / GSTRIPS) * 32;
            const int g4    = strip * 32 + tx;
            if (tid < 32) w2s[tid] = W2[k0 + tid];
            __syncthreads();
            const float4* __restrict__ W14 = reinterpret_cast<const float4*>(W1);
            float4 acc = make_float4(0.f, 0.f, 0.f, 0.f);
            if (g4 < G4_DIM) {
                #pragma unroll
                for (int j = 0; j < 4; j++) {
                    int k = k0 + ty + j * 8;
                    float4 w = __ldg(&W14[(size_t)k * G4_DIM + g4]);
                    float s = w2s[ty + j * 8];
                    acc.x = fmaf(w.x, s, acc.x);
                    acc.y = fmaf(w.y, s, acc.y);
                    acc.z = fmaf(w.z, s, acc.z);
                    acc.w = fmaf(w.w, s, acc.w);
                }
            }
            red[ty][tx] = acc;
            __syncthreads();
            if (ty < 4) {
                float4 o = red[ty + 4][tx];
                acc.x += o.x; acc.y += o.y; acc.z += o.z; acc.w += o.w;
                red[ty][tx] = acc;
            }
            __syncthreads();
            if (ty < 2) {
                float4 o = red[ty + 2][tx];
                acc.x += o.x; acc.y += o.y; acc.z += o.z; acc.w += o.w;
                red[ty][tx] = acc;
            }
            __syncthreads();
            if (ty == 0 && g4 < G4_DIM) {
                float4 o = red[1][tx];
                acc.x += o.x; acc.y += o.y; acc.z += o.z; acc.w += o.w;
                float* vo = &g_v[g4 * 4];
                atomicAdd(vo + 0, acc.x);
                atomicAdd(vo + 1, acc.y);
                atomicAdd(vo + 2, acc.z);
                atomicAdd(vo + 3, acc.w);
            }
            __syncthreads();   // protect w2s/red reuse next unit
        } else {
            const int idx = u - BUILD_UNITS;
            const int i = idx * 256 + tid;
            if (i < S_DIM / 4)
                reinterpret_cast<float4*>(g_coef)[i] = make_float4(0.f, 0.f, 0.f, 0.f);
            if (idx == 0) {
                out[tid] = 0.0f;                 // B_DIM == 256 == NTHR
                if (tid == 0) g_const0 = 0.0f;
            }
        }
    }

    // L2-prefetch this block's phase-2 edge quads (overlaps with W1 stream)
    const int i4 = bid * 256 + tid;
    if (i4 < E_DIM / 4) {
        const int4*   sp = reinterpret_cast<const int4*>(snp) + i4;
        const int4*   gp = reinterpret_cast<const int4*>(gidx) + i4;
        const float4* wp = reinterpret_cast<const float4*>(ew) + i4;
        asm volatile("prefetch.global.L2 [%0];" :: "l"(sp));
        asm volatile("prefetch.global.L2 [%0];" :: "l"(gp));
        asm volatile("prefetch.global.L2 [%0];" :: "l"(wp));
    }

    grid_barrier();

    // ======================= PHASE 2: scatter + const0 =====================
    if (i4 < E_DIM / 4) {
        int4   s4 = __ldg(reinterpret_cast<const int4*>(snp) + i4);
        int4   g4 = __ldg(reinterpret_cast<const int4*>(gidx) + i4);
        float4 w4 = __ldg(reinterpret_cast<const float4*>(ew) + i4);
        float v0 = g_v[g4.x], v1 = g_v[g4.y], v2 = g_v[g4.z], v3 = g_v[g4.w];
        atomicAdd(&g_coef[s4.x], w4.x * v0);
        atomicAdd(&g_coef[s4.y], w4.y * v1);
        atomicAdd(&g_coef[s4.z], w4.z * v2);
        atomicAdd(&g_coef[s4.w], w4.w * v3);
    } else if (bid >= C0_FIRST) {
        // ---- const0: 18 blocks x 1000 genes ----
        const int local = bid - C0_FIRST;            // 0..17
        const int start = local * 1000;
        float acc = 0.0f;
        #pragma unroll
        for (int r = 0; r < 4; r++) {
            int g = start + r * 256 + tid;
            if (g < start + 1000)
                acc = fmaf(g_v[g], gene_bias[g], acc);
        }
        if (local == 0) {
            acc = fmaf(W2[tid], b1[tid], acc);       // H_DIM == 256 == NTHR
            if (tid == 0) acc += b2[0];
        }
        int lane = tid & 31, wid = tid >> 5;
        #pragma unroll
        for (int o = 16; o > 0; o >>= 1) acc += __shfl_down_sync(0xffffffffu, acc, o);
        if (lane == 0) smr[wid] = acc;
        __syncthreads();
        if (tid == 0) {
            float t = 0.0f;
            #pragma unroll
            for (int w = 0; w < 8; w++) t += smr[w];
            atomicAdd(&g_const0, t);
        }
    }

    grid_barrier();

    // ======================= PHASE 3: GEMV =================================
    const float c0 = g_const0;
    const float4* __restrict__ cf = reinterpret_cast<const float4*>(g_coef);

    for (int t = bid; t < NTILES; t += NBLK) {
        const int chunk = t % CHUNKS;
        const int rg    = t / CHUNKS;                // 0..31
        const int base  = chunk * 500;
        const int r0    = rg * ROWS;

        float acc[ROWS];
        #pragma unroll
        for (int j = 0; j < ROWS; j++) acc[j] = 0.0f;

        #pragma unroll
        for (int it = 0; it < 2; it++) {
            int off = it * 256 + tid;
            if (off < 500) {
                int i = base + off;
                float4 cv = __ldg(&cf[i]);
                #pragma unroll
                for (int j = 0; j < ROWS; j++) {
                    float4 xv = __ldcs(reinterpret_cast<const float4*>(
                                    x + (size_t)(r0 + j) * S_DIM) + i);
                    acc[j] += xv.x * cv.x + xv.y * cv.y + xv.z * cv.z + xv.w * cv.w;
                }
            }
        }

        int lane = tid & 31, wid = tid >> 5;
        #pragma unroll
        for (int j = 0; j < ROWS; j++) {
            float v = acc[j];
            #pragma unroll
            for (int o = 16; o > 0; o >>= 1) v += __shfl_down_sync(0xffffffffu, v, o);
            if (lane == 0) smr[j * 8 + wid] = v;
        }
        __syncthreads();
        if (tid < ROWS * 8) {
            int j = tid >> 3, w = tid & 7;
            float v = smr[j * 8 + w];
            #pragma unroll
            for (int o = 4; o > 0; o >>= 1) v += __shfl_down_sync(0xffffffffu, v, o);
            if (w == 0) {
                if (chunk == 0) v += c0;
                atomicAdd(&out[r0 + j], v);
            }
        }
        __syncthreads();   // smr reuse across tiles
    }

    // ---- epilogue: restore g_v == 0 for the next launch (v is dead) ----
    {
        int i = bid * 256 + tid;
        if (i < G_DIM) g_v[i] = 0.0f;
    }
}

// ---------------------------------------------------------------------------
extern "C" void kernel_launch(void* const* d_in, const int* in_sizes, int n_in,
                              void* d_out, int out_size) {
    const float* x    = (const float*)d_in[0];
    const int*   snp  = (const int*)  d_in[1];
    const int*   gidx = (const int*)  d_in[2];
    const float* ew   = (const float*)d_in[3];
    const float* gb   = (const float*)d_in[4];
    const float* W1   = (const float*)d_in[5];
    const float* b1   = (const float*)d_in[6];
    const float* W2   = (const float*)d_in[7];
    const float* b2   = (const float*)d_in[8];
    float* out = (float*)d_out;

    k_fused<<<NBLK, NTHR>>>(W1, W2, snp, gidx, ew, gb, b1, b2, x, out);
}

// round 12
// speedup vs baseline: 1.1383x; 1.1383x over previous
#include <cuda_runtime.h>

#define S_DIM 100000
#define G_DIM 18000
#define H_DIM 256
#define E_DIM 600000
#define B_DIM 256

#define G4_DIM  4500   // G_DIM/4 float4 columns
#define BSTRIPS 36     // ceil(4500/128) gene strips of 128 float4 (2KB)
#define BKT     8      // k-tiles (32 k's each)
#define CHUNKS  50     // gemv chunks along S
#define ROWS    8      // gemv rows per block
#define SCAT_BLOCKS 586   // ceil(150000/256)
#define C0_BLOCKS   9     // const0 tail blocks

// INVARIANT: g_v == 0 at every kernel_launch entry (statically zero at load;
// k_gemv re-zeroes it on exit when v is dead). k_build_v's grid.y==BKT slice
// zeroes coef/out/const0 before their writers run.
__device__ float g_v[G_DIM];
__device__ float g_coef[S_DIM];
__device__ float g_const0;

// ---------------------------------------------------------------------------
// Kernel 1: grid=(BSTRIPS, BKT+1), block=256 (8 warps).
//   y < BKT : tile = 128 float4 genes (2KB span) x 32 k's.
//             Warp w owns k-rows k0+w+8s (s=0..3); each thread loads 4
//             CONSECUTIVE float4 per row (2KB contiguous per warp access
//             group, immediate-offset -> front-batched), 4 rows -> 16 LDG.
//             One sync, 8-warp smem reduce, warps 0..3 do final atomics.
//   y == BKT: zero coef + out + const0.
__global__ void __launch_bounds__(256, 4)
k_build_v(const float* __restrict__ W1, const float* __restrict__ W2,
          float* __restrict__ out) {
    if (blockIdx.y == BKT) {
        float4 z = make_float4(0.f, 0.f, 0.f, 0.f);
        float4* c4 = reinterpret_cast<float4*>(g_coef);
        for (int i = blockIdx.x * 256 + threadIdx.x; i < S_DIM / 4; i += BSTRIPS * 256)
            c4[i] = z;
        if (blockIdx.x == 0) {
            out[threadIdx.x] = 0.0f;                 // B_DIM == 256
            if (threadIdx.x == 0) g_const0 = 0.0f;
        }
        return;
    }
    const int w  = threadIdx.x >> 5;
    const int tx = threadIdx.x & 31;
    const int k0 = blockIdx.y * 32;
    const int gbase = blockIdx.x * 128;              // float4 index

    __shared__ float  w2s[32];
    __shared__ float4 red[8][4][32];                 // 16 KB
    if (threadIdx.x < 32) w2s[threadIdx.x] = W2[k0 + threadIdx.x];
    __syncthreads();

    const float4* __restrict__ W14 = reinterpret_cast<const float4*>(W1);
    float4 acc[4];
    #pragma unroll
    for (int j = 0; j < 4; j++) acc[j] = make_float4(0.f, 0.f, 0.f, 0.f);

    #pragma unroll
    for (int s = 0; s < 4; s++) {
        const int k = k0 + w + 8 * s;
        const float sw = w2s[w + 8 * s];
        const float4* __restrict__ row = W14 + (size_t)k * G4_DIM + gbase;
        #pragma unroll
        for (int j = 0; j < 4; j++) {
            if (gbase + 32 * j + tx < G4_DIM) {      // only last strip partial
                float4 wv = __ldg(row + 32 * j + tx);
                acc[j].x = fmaf(wv.x, sw, acc[j].x);
                acc[j].y = fmaf(wv.y, sw, acc[j].y);
                acc[j].z = fmaf(wv.z, sw, acc[j].z);
                acc[j].w = fmaf(wv.w, sw, acc[j].w);
            }
        }
    }

    #pragma unroll
    for (int j = 0; j < 4; j++) red[w][j][tx] = acc[j];
    __syncthreads();

    if (w < 4) {                                     // warp j reduces chunk j
        const int j = w;
        float4 a = red[0][j][tx];
        #pragma unroll
        for (int r = 1; r < 8; r++) {
            float4 o = red[r][j][tx];
            a.x += o.x; a.y += o.y; a.z += o.z; a.w += o.w;
        }
        const int g4 = gbase + 32 * j + tx;
        if (g4 < G4_DIM) {
            float* vo = &g_v[g4 * 4];
            atomicAdd(vo + 0, a.x);
            atomicAdd(vo + 1, a.y);
            atomicAdd(vo + 2, a.z);
            atomicAdd(vo + 3, a.w);
        }
    }
}

// ---------------------------------------------------------------------------
// Kernel 2: edge scatter (4 edges/thread, vectorized) + const0 tail blocks.
__global__ void k_scatter(const int* __restrict__ snp, const int* __restrict__ gidx,
                          const float* __restrict__ ew,
                          const float* __restrict__ gene_bias,
                          const float* __restrict__ b1, const float* __restrict__ W2,
                          const float* __restrict__ b2) {
    if (blockIdx.x < SCAT_BLOCKS) {
        int i4 = blockIdx.x * blockDim.x + threadIdx.x;     // quad index
        if (i4 >= E_DIM / 4) return;
        int4   s4 = reinterpret_cast<const int4*>(snp)[i4];
        int4   g4 = reinterpret_cast<const int4*>(gidx)[i4];
        float4 w4 = reinterpret_cast<const float4*>(ew)[i4];
        float v0 = g_v[g4.x], v1 = g_v[g4.y], v2 = g_v[g4.z], v3 = g_v[g4.w];
        atomicAdd(&g_coef[s4.x], w4.x * v0);
        atomicAdd(&g_coef[s4.y], w4.y * v1);
        atomicAdd(&g_coef[s4.z], w4.z * v2);
        atomicAdd(&g_coef[s4.w], w4.w * v3);
        return;
    }
    // ---- const0 tail ----
    int local = blockIdx.x - SCAT_BLOCKS;                   // 0..8
    int start = local * (G_DIM / C0_BLOCKS);                // 2000 per block
    float acc = 0.0f;
    for (int g = start + threadIdx.x; g < start + G_DIM / C0_BLOCKS; g += blockDim.x)
        acc = fmaf(g_v[g], gene_bias[g], acc);
    if (local == 0) {
        acc = fmaf(W2[threadIdx.x], b1[threadIdx.x], acc);  // blockDim == H_DIM
        if (threadIdx.x == 0) acc += b2[0];
    }
    __shared__ float sm[32];
    int lane = threadIdx.x & 31, wid = threadIdx.x >> 5;
    #pragma unroll
    for (int o = 16; o > 0; o >>= 1) acc += __shfl_down_sync(0xffffffffu, acc, o);
    if (lane == 0) sm[wid] = acc;
    __syncthreads();
    if (wid == 0) {
        acc = (lane < (blockDim.x >> 5)) ? sm[lane] : 0.0f;
        #pragma unroll
        for (int o = 16; o > 0; o >>= 1) acc += __shfl_down_sync(0xffffffffu, acc, o);
        if (lane == 0) atomicAdd(&g_const0, acc);
    }
}

// ---------------------------------------------------------------------------
// Kernel 3: GEMV (proven config, ~5.1 TB/s). grid=(50,32)=1600.
// Epilogue: blockIdx.x==0 blocks re-zero g_v (dead here) for next launch.
__global__ void __launch_bounds__(256, 6)
k_gemv(const float* __restrict__ x, float* __restrict__ out) {
    const int per  = (S_DIM / 4) / CHUNKS;         // 500
    const int base = blockIdx.x * per;
    const int r0   = blockIdx.y * ROWS;
    const float4* __restrict__ cf = reinterpret_cast<const float4*>(g_coef);

    float acc[ROWS];
    #pragma unroll
    for (int j = 0; j < ROWS; j++) acc[j] = 0.0f;

    #pragma unroll
    for (int it = 0; it < 2; it++) {
        int off = it * 256 + threadIdx.x;
        if (off < per) {
            int i = base + off;
            float4 cv = __ldg(&cf[i]);
            #pragma unroll
            for (int j = 0; j < ROWS; j++) {
                float4 xv = __ldcs(reinterpret_cast<const float4*>(
                                x + (size_t)(r0 + j) * S_DIM) + i);
                acc[j] += xv.x * cv.x + xv.y * cv.y + xv.z * cv.z + xv.w * cv.w;
            }
        }
    }

    __shared__ float sm[ROWS][8];
    int lane = threadIdx.x & 31, wid = threadIdx.x >> 5;
    #pragma unroll
    for (int j = 0; j < ROWS; j++) {
        float v = acc[j];
        #pragma unroll
        for (int o = 16; o > 0; o >>= 1) v += __shfl_down_sync(0xffffffffu, v, o);
        if (lane == 0) sm[j][wid] = v;
    }
    __syncthreads();
    if (threadIdx.x < ROWS * 8) {
        int j = threadIdx.x >> 3, w = threadIdx.x & 7;
        float v = sm[j][w];
        #pragma unroll
        for (int o = 4; o > 0; o >>= 1) v += __shfl_down_sync(0xffffffffu, v, o);
        if (w == 0) {
            if (blockIdx.x == 0) v += g_const0;    // exactly one chunk adds const0
            atomicAdd(&out[r0 + j], v);
        }
    }

    // ---- epilogue: restore g_v == 0 for the next kernel_launch call ----
    if (blockIdx.x == 0) {
        int i = blockIdx.y * 256 + threadIdx.x;    // 8192 threads over 18000
        #pragma unroll
        for (int rep = 0; rep < 3; rep++, i += 8192)
            if (i < G_DIM) g_v[i] = 0.0f;
    }
}

// ---------------------------------------------------------------------------
extern "C" void kernel_launch(void* const* d_in, const int* in_sizes, int n_in,
                              void* d_out, int out_size) {
    const float* x    = (const float*)d_in[0];
    const int*   snp  = (const int*)  d_in[1];
    const int*   gidx = (const int*)  d_in[2];
    const float* ew   = (const float*)d_in[3];
    const float* gb   = (const float*)d_in[4];
    const float* W1   = (const float*)d_in[5];
    const float* b1   = (const float*)d_in[6];
    const float* W2   = (const float*)d_in[7];
    const float* b2   = (const float*)d_in[8];
    float* out = (float*)d_out;

    k_build_v<<<dim3(BSTRIPS, BKT + 1), 256>>>(W1, W2, out);
    k_scatter<<<SCAT_BLOCKS + C0_BLOCKS, 256>>>(snp, gidx, ew, gb, b1, W2, b2);
    k_gemv<<<dim3(CHUNKS, B_DIM / ROWS), 256>>>(x, out);
}

// round 13
// speedup vs baseline: 1.1489x; 1.0093x over previous
#include <cuda_runtime.h>

#define S_DIM 100000
#define G_DIM 18000
#define H_DIM 256
#define E_DIM 600000
#define B_DIM 256

#define G4_DIM  4500   // G_DIM/4 float4 columns
#define BSTRIPS 36     // gene strips of 128 float4 (2KB)
#define BKT     8      // k-tiles (32 k's each)
#define CHUNKS  50     // gemv chunks along S
#define ROWS    8      // gemv rows per block
#define SCAT_BLOCKS 586   // ceil(150000/256)
#define C0_BLOCKS   9     // const0 tail blocks
#define PF_BLOCKS  128    // x-prefetch blocks appended to scatter grid

#define X_LINES    800000 // 102.4 MB / 128B
#define PF1_LINES_PER_THR 32           // build_v slice: 36*256*32 = 294912 lines
#define PF1_TOTAL (BSTRIPS * 256 * PF1_LINES_PER_THR)
#define PF2_LINES_PER_THR 8            // scatter: 128*256*8 = 262144 lines

// INVARIANT: g_v == 0 at every kernel_launch entry (statically zero at load;
// k_gemv re-zeroes it on exit when v is dead). k_build_v's grid.y==BKT slice
// zeroes coef/out/const0 before their writers run.
__device__ float g_v[G_DIM];
__device__ float g_coef[S_DIM];
__device__ float g_const0;

__device__ __forceinline__ void l2_prefetch(const char* p) {
    asm volatile("prefetch.global.L2 [%0];" :: "l"(p));
}

// ---------------------------------------------------------------------------
// Kernel 1: grid=(BSTRIPS, BKT+2), block=256 (8 warps).
//   y < BKT  : build_v tile (proven R12 layout: 2KB warp spans, smem reduce)
//   y == BKT : zero coef + out + const0
//   y == BKT+1: L2-prefetch x lines [0, PF1_TOTAL) — fills the DRAM bandwidth
//              that build_v's latency-bound blocks leave idle.
__global__ void __launch_bounds__(256, 4)
k_build_v(const float* __restrict__ W1, const float* __restrict__ W2,
          float* __restrict__ out, const float* __restrict__ x) {
    if (blockIdx.y == BKT) {
        float4 z = make_float4(0.f, 0.f, 0.f, 0.f);
        float4* c4 = reinterpret_cast<float4*>(g_coef);
        for (int i = blockIdx.x * 256 + threadIdx.x; i < S_DIM / 4; i += BSTRIPS * 256)
            c4[i] = z;
        if (blockIdx.x == 0) {
            out[threadIdx.x] = 0.0f;                 // B_DIM == 256
            if (threadIdx.x == 0) g_const0 = 0.0f;
        }
        return;
    }
    if (blockIdx.y == BKT + 1) {
        const char* xb = reinterpret_cast<const char*>(x);
        int t = blockIdx.x * 256 + threadIdx.x;      // 0..9215
        #pragma unroll
        for (int j = 0; j < PF1_LINES_PER_THR; j++) {
            int line = t + j * (BSTRIPS * 256);
            l2_prefetch(xb + (size_t)line * 128);
        }
        return;
    }
    const int w  = threadIdx.x >> 5;
    const int tx = threadIdx.x & 31;
    const int k0 = blockIdx.y * 32;
    const int gbase = blockIdx.x * 128;              // float4 index

    __shared__ float  w2s[32];
    __shared__ float4 red[8][4][32];                 // 16 KB
    if (threadIdx.x < 32) w2s[threadIdx.x] = W2[k0 + threadIdx.x];
    __syncthreads();

    const float4* __restrict__ W14 = reinterpret_cast<const float4*>(W1);
    float4 acc[4];
    #pragma unroll
    for (int j = 0; j < 4; j++) acc[j] = make_float4(0.f, 0.f, 0.f, 0.f);

    #pragma unroll
    for (int s = 0; s < 4; s++) {
        const int k = k0 + w + 8 * s;
        const float sw = w2s[w + 8 * s];
        const float4* __restrict__ row = W14 + (size_t)k * G4_DIM + gbase;
        #pragma unroll
        for (int j = 0; j < 4; j++) {
            if (gbase + 32 * j + tx < G4_DIM) {
                float4 wv = __ldg(row + 32 * j + tx);
                acc[j].x = fmaf(wv.x, sw, acc[j].x);
                acc[j].y = fmaf(wv.y, sw, acc[j].y);
                acc[j].z = fmaf(wv.z, sw, acc[j].z);
                acc[j].w = fmaf(wv.w, sw, acc[j].w);
            }
        }
    }

    #pragma unroll
    for (int j = 0; j < 4; j++) red[w][j][tx] = acc[j];
    __syncthreads();

    if (w < 4) {
        const int j = w;
        float4 a = red[0][j][tx];
        #pragma unroll
        for (int r = 1; r < 8; r++) {
            float4 o = red[r][j][tx];
            a.x += o.x; a.y += o.y; a.z += o.z; a.w += o.w;
        }
        const int g4 = gbase + 32 * j + tx;
        if (g4 < G4_DIM) {
            float* vo = &g_v[g4 * 4];
            atomicAdd(vo + 0, a.x);
            atomicAdd(vo + 1, a.y);
            atomicAdd(vo + 2, a.z);
            atomicAdd(vo + 3, a.w);
        }
    }
}

// ---------------------------------------------------------------------------
// Kernel 2: edge scatter + const0 tail + x-prefetch blocks.
__global__ void k_scatter(const int* __restrict__ snp, const int* __restrict__ gidx,
                          const float* __restrict__ ew,
                          const float* __restrict__ gene_bias,
                          const float* __restrict__ b1, const float* __restrict__ W2,
                          const float* __restrict__ b2, const float* __restrict__ x) {
    if (blockIdx.x < SCAT_BLOCKS) {
        int i4 = blockIdx.x * blockDim.x + threadIdx.x;     // quad index
        if (i4 >= E_DIM / 4) return;
        int4   s4 = reinterpret_cast<const int4*>(snp)[i4];
        int4   g4 = reinterpret_cast<const int4*>(gidx)[i4];
        float4 w4 = reinterpret_cast<const float4*>(ew)[i4];
        float v0 = g_v[g4.x], v1 = g_v[g4.y], v2 = g_v[g4.z], v3 = g_v[g4.w];
        atomicAdd(&g_coef[s4.x], w4.x * v0);
        atomicAdd(&g_coef[s4.y], w4.y * v1);
        atomicAdd(&g_coef[s4.z], w4.z * v2);
        atomicAdd(&g_coef[s4.w], w4.w * v3);
        return;
    }
    if (blockIdx.x >= SCAT_BLOCKS + C0_BLOCKS) {
        // ---- x prefetch: lines [PF1_TOTAL, PF1_TOTAL + 128*256*8) ----
        const char* xb = reinterpret_cast<const char*>(x);
        int t = (blockIdx.x - SCAT_BLOCKS - C0_BLOCKS) * 256 + threadIdx.x;
        #pragma unroll
        for (int j = 0; j < PF2_LINES_PER_THR; j++) {
            int line = PF1_TOTAL + t + j * (PF_BLOCKS * 256);
            if (line < X_LINES) l2_prefetch(xb + (size_t)line * 128);
        }
        return;
    }
    // ---- const0 tail ----
    int local = blockIdx.x - SCAT_BLOCKS;                   // 0..8
    int start = local * (G_DIM / C0_BLOCKS);                // 2000 per block
    float acc = 0.0f;
    for (int g = start + threadIdx.x; g < start + G_DIM / C0_BLOCKS; g += blockDim.x)
        acc = fmaf(g_v[g], gene_bias[g], acc);
    if (local == 0) {
        acc = fmaf(W2[threadIdx.x], b1[threadIdx.x], acc);  // blockDim == H_DIM
        if (threadIdx.x == 0) acc += b2[0];
    }
    __shared__ float sm[32];
    int lane = threadIdx.x & 31, wid = threadIdx.x >> 5;
    #pragma unroll
    for (int o = 16; o > 0; o >>= 1) acc += __shfl_down_sync(0xffffffffu, acc, o);
    if (lane == 0) sm[wid] = acc;
    __syncthreads();
    if (wid == 0) {
        acc = (lane < (blockDim.x >> 5)) ? sm[lane] : 0.0f;
        #pragma unroll
        for (int o = 16; o > 0; o >>= 1) acc += __shfl_down_sync(0xffffffffu, acc, o);
        if (lane == 0) atomicAdd(&g_const0, acc);
    }
}

// ---------------------------------------------------------------------------
// Kernel 3: GEMV (frozen proven config). grid=(50,32)=1600.
// ~71 MB of x is now L2-resident from the prefetch blocks.
__global__ void __launch_bounds__(256, 6)
k_gemv(const float* __restrict__ x, float* __restrict__ out) {
    const int per  = (S_DIM / 4) / CHUNKS;         // 500
    const int base = blockIdx.x * per;
    const int r0   = blockIdx.y * ROWS;
    const float4* __restrict__ cf = reinterpret_cast<const float4*>(g_coef);

    float acc[ROWS];
    #pragma unroll
    for (int j = 0; j < ROWS; j++) acc[j] = 0.0f;

    #pragma unroll
    for (int it = 0; it < 2; it++) {
        int off = it * 256 + threadIdx.x;
        if (off < per) {
            int i = base + off;
            float4 cv = __ldg(&cf[i]);
            #pragma unroll
            for (int j = 0; j < ROWS; j++) {
                float4 xv = __ldcs(reinterpret_cast<const float4*>(
                                x + (size_t)(r0 + j) * S_DIM) + i);
                acc[j] += xv.x * cv.x + xv.y * cv.y + xv.z * cv.z + xv.w * cv.w;
            }
        }
    }

    __shared__ float sm[ROWS][8];
    int lane = threadIdx.x & 31, wid = threadIdx.x >> 5;
    #pragma unroll
    for (int j = 0; j < ROWS; j++) {
        float v = acc[j];
        #pragma unroll
        for (int o = 16; o > 0; o >>= 1) v += __shfl_down_sync(0xffffffffu, v, o);
        if (lane == 0) sm[j][wid] = v;
    }
    __syncthreads();
    if (threadIdx.x < ROWS * 8) {
        int j = threadIdx.x >> 3, w = threadIdx.x & 7;
        float v = sm[j][w];
        #pragma unroll
        for (int o = 4; o > 0; o >>= 1) v += __shfl_down_sync(0xffffffffu, v, o);
        if (w == 0) {
            if (blockIdx.x == 0) v += g_const0;
            atomicAdd(&out[r0 + j], v);
        }
    }

    // ---- epilogue: restore g_v == 0 for the next kernel_launch call ----
    if (blockIdx.x == 0) {
        int i = blockIdx.y * 256 + threadIdx.x;
        #pragma unroll
        for (int rep = 0; rep < 3; rep++, i += 8192)
            if (i < G_DIM) g_v[i] = 0.0f;
    }
}

// ---------------------------------------------------------------------------
extern "C" void kernel_launch(void* const* d_in, const int* in_sizes, int n_in,
                              void* d_out, int out_size) {
    const float* x    = (const float*)d_in[0];
    const int*   snp  = (const int*)  d_in[1];
    const int*   gidx = (const int*)  d_in[2];
    const float* ew   = (const float*)d_in[3];
    const float* gb   = (const float*)d_in[4];
    const float* W1   = (const float*)d_in[5];
    const float* b1   = (const float*)d_in[6];
    const float* W2   = (const float*)d_in[7];
    const float* b2   = (const float*)d_in[8];
    float* out = (float*)d_out;

    k_build_v<<<dim3(BSTRIPS, BKT + 2), 256>>>(W1, W2, out, x);
    k_scatter<<<SCAT_BLOCKS + C0_BLOCKS + PF_BLOCKS, 256>>>(snp, gidx, ew, gb, b1, W2, b2, x);
    k_gemv<<<dim3(CHUNKS, B_DIM / ROWS), 256>>>(x, out);
}